// round 2
// baseline (speedup 1.0000x reference)
#include <cuda_runtime.h>

#define D      3072
#define BATCH  512
#define NC     100
#define RS     48      // row splits for column-sum kernel
#define RROWS  64      // rows per split (48*64 = 3072)
#define BK     32      // GEMM k-tile
#define NSPLIT 96      // D / BK
#define BM     128     // GEMM m-tile
#define MT     4       // BATCH / BM
#define ZSTR   65      // Zs row stride (odd -> conflict-free rg access)
#define WSTR   102     // Wt row stride (even -> aligned float2)

// ---- device scratch (static, no allocation) ----
__device__ float g_pA[RS * D];
__device__ float g_pB[RS * D];
__device__ float g_colA[D];
__device__ float g_colB[D];
__device__ float g_fcrow[NC];
__device__ float g_part1;
__device__ float g_scratch[NSPLIT * BATCH * NC];   // 19.66 MB (L2-resident)

// ---- f32x2 packed-FMA helpers (sm_103a FFMA2) ----
__device__ __forceinline__ unsigned long long pk2(float lo, float hi) {
    unsigned long long r;
    asm("mov.b64 %0, {%1, %2};" : "=l"(r) : "f"(lo), "f"(hi));
    return r;
}
__device__ __forceinline__ void fma2(unsigned long long& d,
                                     unsigned long long a,
                                     unsigned long long b) {
    asm("fma.rn.f32x2 %0, %1, %2, %0;" : "+l"(d) : "l"(a), "l"(b));
}
__device__ __forceinline__ float2 up2(unsigned long long v) {
    float2 f;
    asm("mov.b64 {%0, %1}, %2;" : "=f"(f.x), "=f"(f.y) : "l"(v));
    return f;
}

// ============================================================
// K1: partial column sums of a and b (vectorized float4).
// grid (3, 48, 2), block 256. Coalesced LDG.128 streaming.
// ============================================================
__global__ void k1_colsum_partial(const float4* __restrict__ a,
                                  const float4* __restrict__ b) {
    int d4 = blockIdx.x * 256 + threadIdx.x;       // 0..767
    int rs = blockIdx.y;
    const float4* src = (blockIdx.z == 0) ? a : b;
    float*        dst = (blockIdx.z == 0) ? g_pA : g_pB;
    const float4* p = src + rs * RROWS * (D / 4) + d4;
    float4 acc = make_float4(0.f, 0.f, 0.f, 0.f);
#pragma unroll 8
    for (int r = 0; r < RROWS; r++) {
        float4 v = p[r * (D / 4)];
        acc.x += v.x; acc.y += v.y; acc.z += v.z; acc.w += v.w;
    }
    *reinterpret_cast<float4*>(dst + rs * D + d4 * 4) = acc;
}

// ============================================================
// K2: finalize column sums; fc_w row sums; scalar part1.
// ============================================================
__global__ void k2_finalize(const float* __restrict__ fc_w,
                            const float* __restrict__ w,
                            const float* __restrict__ n_param) {
    int bx = blockIdx.x, t = threadIdx.x;
    if (bx < 12) {
        int d = bx * 256 + t;
        float sa = 0.f, sb = 0.f;
#pragma unroll 8
        for (int s = 0; s < RS; s++) {
            sa += g_pA[s * D + d];
            sb += g_pB[s * D + d];
        }
        g_colA[d] = sa;
        g_colB[d] = sb;
    } else {
        int c    = (bx - 12) * 8 + (t >> 5);
        int lane = t & 31;
        if (c < NC) {
            float s = 0.f;
            for (int j = lane; j < D; j += 32) s += fc_w[c * D + j];
#pragma unroll
            for (int o = 16; o; o >>= 1) s += __shfl_xor_sync(0xffffffffu, s, o);
            if (lane == 0) g_fcrow[c] = s;
        }
        if (bx == 24 && t == 0) {
            float p1 = 0.f;
#pragma unroll
            for (int i = 0; i < 4; i++)
                p1 += w[i + 1] * n_param[i + 1] + w[i] * n_param[i];
            g_part1 = p1;
        }
    }
}

// ============================================================
// K3: fused split-K GEMM with packed f32x2 FMA.
//   Z[b,d] = cos(x[b,d])*colA[d] + sin(x[b,d])*colB[d]  (on the fly)
//   scratch[split][b][c] = Z-tile @ W-tile^T
// grid (4, 96), block 160 (5 warps). Micro-tile 8 rows x 10 cols,
// cols packed in pairs -> 40 FFMA2 per k-step per thread.
// W stored transposed in smem (Wt[k][c]) so col-pairs are contiguous.
// Row map rg+16m -> z LDS conflict-free (stride 65, 16 banks).
// ============================================================
__global__ __launch_bounds__(160, 3)
void k3_gemm(const float* __restrict__ xf, const float* __restrict__ fc_w) {
    __shared__ float Zs[BM * ZSTR];    // 128*65  = 33.3 KB
    __shared__ float Wt[BK * WSTR];    // 32*102  = 13.1 KB

    const int t     = threadIdx.x;
    const int mtile = blockIdx.x;
    const int split = blockIdx.y;
    const int k0    = split * BK;

    // ---- Z tile: load x as float4, sincos fused ----
    for (int i = t; i < BM * (BK / 4); i += 160) {
        int row = i >> 3;              // BK/4 = 8 quads per row
        int kq  = i & 7;
        float4 v = *reinterpret_cast<const float4*>(
            xf + (mtile * BM + row) * D + k0 + kq * 4);
        float vv[4] = {v.x, v.y, v.z, v.w};
#pragma unroll
        for (int j = 0; j < 4; j++) {
            int kk = kq * 4 + j;
            float sn, cs;
            __sincosf(vv[j], &sn, &cs);
            Zs[row * ZSTR + kk] = cs * g_colA[k0 + kk] + sn * g_colB[k0 + kk];
        }
    }
    // ---- W tile: load rows, store transposed ----
    for (int i = t; i < NC * (BK / 4); i += 160) {
        int c  = i >> 3;
        int kq = i & 7;
        float4 v = *reinterpret_cast<const float4*>(fc_w + c * D + k0 + kq * 4);
        Wt[(kq * 4 + 0) * WSTR + c] = v.x;
        Wt[(kq * 4 + 1) * WSTR + c] = v.y;
        Wt[(kq * 4 + 2) * WSTR + c] = v.z;
        Wt[(kq * 4 + 3) * WSTR + c] = v.w;
    }
    __syncthreads();

    const int rg = t & 15;     // 16 row groups, rows rg + 16*m
    const int cg = t >> 4;     // 10 col groups, cols cg*10 .. cg*10+9

    unsigned long long acc[8][5];
#pragma unroll
    for (int m = 0; m < 8; m++)
#pragma unroll
        for (int n = 0; n < 5; n++) acc[m][n] = 0ull;

#pragma unroll 2
    for (int k = 0; k < BK; k++) {
        unsigned long long wv[5];
        const float* wrow = &Wt[k * WSTR + cg * 10];
#pragma unroll
        for (int n = 0; n < 5; n++) {
            float2 wp = *reinterpret_cast<const float2*>(wrow + 2 * n);
            wv[n] = pk2(wp.x, wp.y);
        }
#pragma unroll
        for (int m = 0; m < 8; m++) {
            float z = Zs[(rg + 16 * m) * ZSTR + k];
            unsigned long long zz = pk2(z, z);
#pragma unroll
            for (int n = 0; n < 5; n++) fma2(acc[m][n], zz, wv[n]);
        }
    }

    // ---- store to split scratch (aligned float2 stores) ----
    float* base = g_scratch + split * (BATCH * NC) + (mtile * BM) * NC + cg * 10;
#pragma unroll
    for (int m = 0; m < 8; m++) {
        float* rowp = base + (rg + 16 * m) * NC;
#pragma unroll
        for (int n = 0; n < 5; n++) {
            float2 v = up2(acc[m][n]);
            *reinterpret_cast<float2*>(rowp + 2 * n) = v;
        }
    }
}

// ============================================================
// K4: reduce splits + part1 * rowsum(fc_w) + fc_b -> out[b][c]
// grid 200 x 256; deep unroll for MLP (all loads L2-resident).
// ============================================================
__global__ void k4_final(const float* __restrict__ fc_b, float* __restrict__ out) {
    int idx = blockIdx.x * 256 + threadIdx.x;
    if (idx >= BATCH * NC) return;
    int c = idx % NC;
    float s = 0.f;
#pragma unroll 24
    for (int sp = 0; sp < NSPLIT; sp++) s += g_scratch[sp * (BATCH * NC) + idx];
    out[idx] = s + g_part1 * g_fcrow[c] + fc_b[c];
}

// ============================================================
extern "C" void kernel_launch(void* const* d_in, const int* in_sizes, int n_in,
                              void* d_out, int out_size) {
    const float* x       = (const float*)d_in[0];   // [512,3072]
    const float* a       = (const float*)d_in[1];   // [3072,3072,1]
    const float* b       = (const float*)d_in[2];   // [3072,3072,1]
    const float* w       = (const float*)d_in[3];   // [5]
    const float* n_param = (const float*)d_in[4];   // [5]
    const float* fc_w    = (const float*)d_in[5];   // [100,3072]
    const float* fc_b    = (const float*)d_in[6];   // [100]
    float* out = (float*)d_out;                     // [512,100]

    k1_colsum_partial<<<dim3(3, RS, 2), 256>>>((const float4*)a, (const float4*)b);
    k2_finalize<<<25, 256>>>(fc_w, w, n_param);
    k3_gemm<<<dim3(MT, NSPLIT), 160>>>(x, fc_w);
    k4_final<<<200, 256>>>(fc_b, out);
}

// round 3
// speedup vs baseline: 1.0336x; 1.0336x over previous
#include <cuda_runtime.h>

#define D      3072
#define BATCH  512
#define NC     100
#define RS     48      // row splits for column-sum kernel
#define RROWS  64      // rows per split (48*64 = 3072)
#define BK     32      // GEMM k-tile
#define NSPLIT 96      // D / BK
#define BM     128     // GEMM m-tile
#define MT     4       // BATCH / BM
#define ZSTR   65      // Zs row stride (odd -> conflict-free rg access)
#define WSTR   102     // Wt row stride (even -> aligned float2)

// ---- device scratch (static, no allocation) ----
__device__ float g_pA[RS * D];
__device__ float g_pB[RS * D];
__device__ float g_colA[D];
__device__ float g_colB[D];
__device__ float g_fcrow[NC];
__device__ float g_part1;
__device__ float g_scratch[NSPLIT * BATCH * NC];   // 19.66 MB (L2-resident)

// ---- f32x2 packed-FMA helpers (sm_103a FFMA2) ----
__device__ __forceinline__ unsigned long long pk2(float lo, float hi) {
    unsigned long long r;
    asm("mov.b64 %0, {%1, %2};" : "=l"(r) : "f"(lo), "f"(hi));
    return r;
}
__device__ __forceinline__ void fma2(unsigned long long& d,
                                     unsigned long long a,
                                     unsigned long long b) {
    asm("fma.rn.f32x2 %0, %1, %2, %0;" : "+l"(d) : "l"(a), "l"(b));
}
__device__ __forceinline__ float2 up2(unsigned long long v) {
    float2 f;
    asm("mov.b64 {%0, %1}, %2;" : "=f"(f.x), "=f"(f.y) : "l"(v));
    return f;
}

// ============================================================
// K1: partial column sums of a and b (vectorized float4).
// grid (3, 48, 2), block 256. Coalesced LDG.128 streaming.
// ============================================================
__global__ void k1_colsum_partial(const float4* __restrict__ a,
                                  const float4* __restrict__ b) {
    int d4 = blockIdx.x * 256 + threadIdx.x;       // 0..767
    int rs = blockIdx.y;
    const float4* src = (blockIdx.z == 0) ? a : b;
    float*        dst = (blockIdx.z == 0) ? g_pA : g_pB;
    const float4* p = src + rs * RROWS * (D / 4) + d4;
    float4 acc = make_float4(0.f, 0.f, 0.f, 0.f);
#pragma unroll 8
    for (int r = 0; r < RROWS; r++) {
        float4 v = p[r * (D / 4)];
        acc.x += v.x; acc.y += v.y; acc.z += v.z; acc.w += v.w;
    }
    *reinterpret_cast<float4*>(dst + rs * D + d4 * 4) = acc;
}

// ============================================================
// K2: finalize column sums; fc_w row sums; scalar part1.
// ============================================================
__global__ void k2_finalize(const float* __restrict__ fc_w,
                            const float* __restrict__ w,
                            const float* __restrict__ n_param) {
    int bx = blockIdx.x, t = threadIdx.x;
    if (bx < 12) {
        int d = bx * 256 + t;
        float sa = 0.f, sb = 0.f;
#pragma unroll 8
        for (int s = 0; s < RS; s++) {
            sa += g_pA[s * D + d];
            sb += g_pB[s * D + d];
        }
        g_colA[d] = sa;
        g_colB[d] = sb;
    } else {
        int c    = (bx - 12) * 8 + (t >> 5);
        int lane = t & 31;
        if (c < NC) {
            float s = 0.f;
            for (int j = lane; j < D; j += 32) s += fc_w[c * D + j];
#pragma unroll
            for (int o = 16; o; o >>= 1) s += __shfl_xor_sync(0xffffffffu, s, o);
            if (lane == 0) g_fcrow[c] = s;
        }
        if (bx == 24 && t == 0) {
            float p1 = 0.f;
#pragma unroll
            for (int i = 0; i < 4; i++)
                p1 += w[i + 1] * n_param[i + 1] + w[i] * n_param[i];
            g_part1 = p1;
        }
    }
}

// ============================================================
// K3: fused split-K GEMM with packed f32x2 FMA.
//   Z[b,d] = cos(x[b,d])*colA[d] + sin(x[b,d])*colB[d]  (on the fly)
//   scratch[split][b][c] = Z-tile @ W-tile^T
// grid (4, 96), block 160 (5 warps). Micro-tile 8 rows x 10 cols,
// cols packed in pairs -> 40 FFMA2 per k-step per thread.
// W stored transposed in smem (Wt[k][c]) so col-pairs are contiguous.
// Row map rg+16m -> z LDS conflict-free (stride 65, 16 banks).
// ============================================================
__global__ __launch_bounds__(160, 3)
void k3_gemm(const float* __restrict__ xf, const float* __restrict__ fc_w) {
    __shared__ float Zs[BM * ZSTR];    // 128*65  = 33.3 KB
    __shared__ float Wt[BK * WSTR];    // 32*102  = 13.1 KB

    const int t     = threadIdx.x;
    const int mtile = blockIdx.x;
    const int split = blockIdx.y;
    const int k0    = split * BK;

    // ---- Z tile: load x as float4, sincos fused ----
    for (int i = t; i < BM * (BK / 4); i += 160) {
        int row = i >> 3;              // BK/4 = 8 quads per row
        int kq  = i & 7;
        float4 v = *reinterpret_cast<const float4*>(
            xf + (mtile * BM + row) * D + k0 + kq * 4);
        float vv[4] = {v.x, v.y, v.z, v.w};
#pragma unroll
        for (int j = 0; j < 4; j++) {
            int kk = kq * 4 + j;
            float sn, cs;
            __sincosf(vv[j], &sn, &cs);
            Zs[row * ZSTR + kk] = cs * g_colA[k0 + kk] + sn * g_colB[k0 + kk];
        }
    }
    // ---- W tile: load rows, store transposed ----
    for (int i = t; i < NC * (BK / 4); i += 160) {
        int c  = i >> 3;
        int kq = i & 7;
        float4 v = *reinterpret_cast<const float4*>(fc_w + c * D + k0 + kq * 4);
        Wt[(kq * 4 + 0) * WSTR + c] = v.x;
        Wt[(kq * 4 + 1) * WSTR + c] = v.y;
        Wt[(kq * 4 + 2) * WSTR + c] = v.z;
        Wt[(kq * 4 + 3) * WSTR + c] = v.w;
    }
    __syncthreads();

    const int rg = t & 15;     // 16 row groups, rows rg + 16*m
    const int cg = t >> 4;     // 10 col groups, cols cg*10 .. cg*10+9

    unsigned long long acc[8][5];
#pragma unroll
    for (int m = 0; m < 8; m++)
#pragma unroll
        for (int n = 0; n < 5; n++) acc[m][n] = 0ull;

#pragma unroll 2
    for (int k = 0; k < BK; k++) {
        unsigned long long wv[5];
        const float* wrow = &Wt[k * WSTR + cg * 10];
#pragma unroll
        for (int n = 0; n < 5; n++) {
            float2 wp = *reinterpret_cast<const float2*>(wrow + 2 * n);
            wv[n] = pk2(wp.x, wp.y);
        }
#pragma unroll
        for (int m = 0; m < 8; m++) {
            float z = Zs[(rg + 16 * m) * ZSTR + k];
            unsigned long long zz = pk2(z, z);
#pragma unroll
            for (int n = 0; n < 5; n++) fma2(acc[m][n], zz, wv[n]);
        }
    }

    // ---- store to split scratch (aligned float2 stores) ----
    float* base = g_scratch + split * (BATCH * NC) + (mtile * BM) * NC + cg * 10;
#pragma unroll
    for (int m = 0; m < 8; m++) {
        float* rowp = base + (rg + 16 * m) * NC;
#pragma unroll
        for (int n = 0; n < 5; n++) {
            float2 v = up2(acc[m][n]);
            *reinterpret_cast<float2*>(rowp + 2 * n) = v;
        }
    }
}

// ============================================================
// K4: reduce splits + part1 * rowsum(fc_w) + fc_b -> out[b][c]
// grid 200 x 256; deep unroll for MLP (all loads L2-resident).
// ============================================================
__global__ void k4_final(const float* __restrict__ fc_b, float* __restrict__ out) {
    int idx = blockIdx.x * 256 + threadIdx.x;
    if (idx >= BATCH * NC) return;
    int c = idx % NC;
    float s = 0.f;
#pragma unroll 24
    for (int sp = 0; sp < NSPLIT; sp++) s += g_scratch[sp * (BATCH * NC) + idx];
    out[idx] = s + g_part1 * g_fcrow[c] + fc_b[c];
}

// ============================================================
extern "C" void kernel_launch(void* const* d_in, const int* in_sizes, int n_in,
                              void* d_out, int out_size) {
    const float* x       = (const float*)d_in[0];   // [512,3072]
    const float* a       = (const float*)d_in[1];   // [3072,3072,1]
    const float* b       = (const float*)d_in[2];   // [3072,3072,1]
    const float* w       = (const float*)d_in[3];   // [5]
    const float* n_param = (const float*)d_in[4];   // [5]
    const float* fc_w    = (const float*)d_in[5];   // [100,3072]
    const float* fc_b    = (const float*)d_in[6];   // [100]
    float* out = (float*)d_out;                     // [512,100]

    k1_colsum_partial<<<dim3(3, RS, 2), 256>>>((const float4*)a, (const float4*)b);
    k2_finalize<<<25, 256>>>(fc_w, w, n_param);
    k3_gemm<<<dim3(MT, NSPLIT), 160>>>(x, fc_w);
    k4_final<<<200, 256>>>(fc_b, out);
}

// round 4
// speedup vs baseline: 1.3078x; 1.2653x over previous
#include <cuda_runtime.h>

#define D      3072
#define BATCH  512
#define NC     100
#define RS     48      // row splits for column-sum kernel
#define RROWS  64      // rows per split (48*64 = 3072)
#define BK     96      // GEMM k-tile per CTA
#define KC     32      // k-chunk staged in smem
#define NSPLIT 32      // D / BK
#define BM     128     // GEMM m-tile
#define MT     4       // BATCH / BM
#define ZSTR   33      // Zs row stride (33 mod 32 = 1 -> conflict-free)
#define WSTR   102     // Wt row stride (even -> aligned float2 reads)
#define OSTR   101     // output staging stride (odd -> conflict-free)

// ---- device scratch (static, no allocation) ----
__device__ float g_pA[RS * D];
__device__ float g_pB[RS * D];
__device__ float g_colA[D];
__device__ float g_colB[D];
__device__ float g_fcrow[NC];
__device__ float g_part1;
__device__ float g_scratch[NSPLIT * BATCH * NC];   // 6.55 MB (L2-resident)

// ---- f32x2 packed-FMA helpers (sm_103a FFMA2) ----
__device__ __forceinline__ unsigned long long pk2(float lo, float hi) {
    unsigned long long r;
    asm("mov.b64 %0, {%1, %2};" : "=l"(r) : "f"(lo), "f"(hi));
    return r;
}
__device__ __forceinline__ void fma2(unsigned long long& d,
                                     unsigned long long a,
                                     unsigned long long b) {
    asm("fma.rn.f32x2 %0, %1, %2, %0;" : "+l"(d) : "l"(a), "l"(b));
}
__device__ __forceinline__ float2 up2(unsigned long long v) {
    float2 f;
    asm("mov.b64 {%0, %1}, %2;" : "=f"(f.x), "=f"(f.y) : "l"(v));
    return f;
}

// ============================================================
// K1: partial column sums of a and b (vectorized float4).
// grid (3, 48, 2), block 256. Coalesced LDG.128 streaming; HBM-bound.
// ============================================================
__global__ void k1_colsum_partial(const float4* __restrict__ a,
                                  const float4* __restrict__ b) {
    int d4 = blockIdx.x * 256 + threadIdx.x;       // 0..767
    int rs = blockIdx.y;
    const float4* src = (blockIdx.z == 0) ? a : b;
    float*        dst = (blockIdx.z == 0) ? g_pA : g_pB;
    const float4* p = src + rs * RROWS * (D / 4) + d4;
    float4 acc = make_float4(0.f, 0.f, 0.f, 0.f);
#pragma unroll 8
    for (int r = 0; r < RROWS; r++) {
        float4 v = p[r * (D / 4)];
        acc.x += v.x; acc.y += v.y; acc.z += v.z; acc.w += v.w;
    }
    *reinterpret_cast<float4*>(dst + rs * D + d4 * 4) = acc;
}

// ============================================================
// K2: finalize column sums; fc_w row sums; scalar part1.
// ============================================================
__global__ void k2_finalize(const float* __restrict__ fc_w,
                            const float* __restrict__ w,
                            const float* __restrict__ n_param) {
    int bx = blockIdx.x, t = threadIdx.x;
    if (bx < 12) {
        int d = bx * 256 + t;
        float sa = 0.f, sb = 0.f;
#pragma unroll 8
        for (int s = 0; s < RS; s++) {
            sa += g_pA[s * D + d];
            sb += g_pB[s * D + d];
        }
        g_colA[d] = sa;
        g_colB[d] = sb;
    } else {
        int c    = (bx - 12) * 8 + (t >> 5);
        int lane = t & 31;
        if (c < NC) {
            float s = 0.f;
            for (int j = lane; j < D; j += 32) s += fc_w[c * D + j];
#pragma unroll
            for (int o = 16; o; o >>= 1) s += __shfl_xor_sync(0xffffffffu, s, o);
            if (lane == 0) g_fcrow[c] = s;
        }
        if (bx == 24 && t == 0) {
            float p1 = 0.f;
#pragma unroll
            for (int i = 0; i < 4; i++)
                p1 += w[i + 1] * n_param[i + 1] + w[i] * n_param[i];
            g_part1 = p1;
        }
    }
}

// ============================================================
// K3: fused split-K GEMM with packed f32x2 FMA.
//   Z[b,d] = cos(x[b,d])*colA[d] + sin(x[b,d])*colB[d]  (on the fly)
//   scratch[split][b][c] = Z-tile[128 x 96] @ W-tile[100 x 96]^T
// grid (4, 32) = 128 CTAs (one wave), block 320 (10 warps).
// Micro-tile: lane -> 4 rows (lane+32m), warp -> 10 cols (5 f32x2 pairs).
// W LDS are warp-uniform (broadcast); z LDS conflict-free (stride 33).
// 20 u64 accumulators (40 regs) -> no spill at 102-reg cap.
// Epilogue staged via smem (2 halves) for coalesced global stores.
// ============================================================
__global__ __launch_bounds__(320, 2)
void k3_gemm(const float* __restrict__ xf, const float* __restrict__ fc_w) {
    __shared__ float sm[BM * ZSTR + KC * WSTR];   // 4224 + 3264 = 7488 f = 29.9KB
    float* Zs = sm;                                // [128][33]
    float* Wt = sm + BM * ZSTR;                    // [32][102]

    const int t     = threadIdx.x;
    const int lane  = t & 31;
    const int wrp   = t >> 5;                      // 0..9 -> column group
    const int mtile = blockIdx.x;
    const int split = blockIdx.y;
    const int k0    = split * BK;

    unsigned long long acc[4][5];
#pragma unroll
    for (int m = 0; m < 4; m++)
#pragma unroll
        for (int n = 0; n < 5; n++) acc[m][n] = 0ull;

    for (int chunk = 0; chunk < BK / KC; chunk++) {
        const int kc = k0 + chunk * KC;

        // ---- Z chunk: 128 rows x 8 quads ----
        for (int i = t; i < BM * (KC / 4); i += 320) {
            int row = i >> 3;
            int kq  = i & 7;
            float4 v = *reinterpret_cast<const float4*>(
                xf + (mtile * BM + row) * D + kc + kq * 4);
            float vv[4] = {v.x, v.y, v.z, v.w};
#pragma unroll
            for (int j = 0; j < 4; j++) {
                int kk = kq * 4 + j;
                float sn, cs;
                __sincosf(vv[j], &sn, &cs);
                Zs[row * ZSTR + kk] =
                    cs * g_colA[kc + kk] + sn * g_colB[kc + kk];
            }
        }
        // ---- W chunk: 100 rows x 8 quads, stored transposed ----
        for (int i = t; i < NC * (KC / 4); i += 320) {
            int c  = i >> 3;
            int kq = i & 7;
            float4 v = *reinterpret_cast<const float4*>(fc_w + c * D + kc + kq * 4);
            Wt[(kq * 4 + 0) * WSTR + c] = v.x;
            Wt[(kq * 4 + 1) * WSTR + c] = v.y;
            Wt[(kq * 4 + 2) * WSTR + c] = v.z;
            Wt[(kq * 4 + 3) * WSTR + c] = v.w;
        }
        __syncthreads();

#pragma unroll 4
        for (int k = 0; k < KC; k++) {
            unsigned long long wv[5];
            const float* wrow = &Wt[k * WSTR + wrp * 10];
#pragma unroll
            for (int n = 0; n < 5; n++) {
                float2 wp = *reinterpret_cast<const float2*>(wrow + 2 * n);
                wv[n] = pk2(wp.x, wp.y);
            }
#pragma unroll
            for (int m = 0; m < 4; m++) {
                float z = Zs[(lane + 32 * m) * ZSTR + k];
                unsigned long long zz = pk2(z, z);
#pragma unroll
                for (int n = 0; n < 5; n++) fma2(acc[m][n], zz, wv[n]);
            }
        }
        __syncthreads();
    }

    // ---- epilogue: stage in smem (2 halves), coalesced stores ----
    float* stage = sm;    // reuse: need 64*101 = 6464 <= 7488 floats
#pragma unroll
    for (int half = 0; half < 2; half++) {
#pragma unroll
        for (int m2 = 0; m2 < 2; m2++) {
            int m = half * 2 + m2;
            int r = lane + 32 * m2;                // 0..63 local row
#pragma unroll
            for (int n = 0; n < 5; n++) {
                float2 v = up2(acc[m][n]);
                stage[r * OSTR + wrp * 10 + 2 * n]     = v.x;
                stage[r * OSTR + wrp * 10 + 2 * n + 1] = v.y;
            }
        }
        __syncthreads();
        float* dst = g_scratch + split * (BATCH * NC)
                   + (mtile * BM + half * 64) * NC;
        for (int i = t; i < 64 * NC; i += 320) {
            int row = i / NC;
            int c   = i - row * NC;
            dst[i] = stage[row * OSTR + c];
        }
        __syncthreads();
    }
}

// ============================================================
// K4: reduce 32 splits + part1 * rowsum(fc_w) + fc_b -> out[b][c]
// Explicit 8-deep load batches to force MLP (R1/R2 had regs=22 -> MLP~2).
// ============================================================
__global__ void k4_final(const float* __restrict__ fc_b, float* __restrict__ out) {
    int idx = blockIdx.x * 256 + threadIdx.x;
    if (idx >= BATCH * NC) return;
    float acc0 = 0.f, acc1 = 0.f, acc2 = 0.f, acc3 = 0.f;
#pragma unroll
    for (int base = 0; base < NSPLIT; base += 8) {
        float v[8];
#pragma unroll
        for (int j = 0; j < 8; j++)
            v[j] = g_scratch[(base + j) * (BATCH * NC) + idx];
        acc0 += v[0] + v[4];
        acc1 += v[1] + v[5];
        acc2 += v[2] + v[6];
        acc3 += v[3] + v[7];
    }
    int c = idx % NC;
    out[idx] = (acc0 + acc1) + (acc2 + acc3) + g_part1 * g_fcrow[c] + fc_b[c];
}

// ============================================================
extern "C" void kernel_launch(void* const* d_in, const int* in_sizes, int n_in,
                              void* d_out, int out_size) {
    const float* x       = (const float*)d_in[0];   // [512,3072]
    const float* a       = (const float*)d_in[1];   // [3072,3072,1]
    const float* b       = (const float*)d_in[2];   // [3072,3072,1]
    const float* w       = (const float*)d_in[3];   // [5]
    const float* n_param = (const float*)d_in[4];   // [5]
    const float* fc_w    = (const float*)d_in[5];   // [100,3072]
    const float* fc_b    = (const float*)d_in[6];   // [100]
    float* out = (float*)d_out;                     // [512,100]

    k1_colsum_partial<<<dim3(3, RS, 2), 256>>>((const float4*)a, (const float4*)b);
    k2_finalize<<<25, 256>>>(fc_w, w, n_param);
    k3_gemm<<<dim3(MT, NSPLIT), 320>>>(x, fc_w);
    k4_final<<<200, 256>>>(fc_b, out);
}

// round 5
// speedup vs baseline: 1.3179x; 1.0077x over previous
#include <cuda_runtime.h>

#define D      3072
#define BATCH  512
#define NC     100
#define RS     48      // row splits for column-sum kernel
#define RROWS  64      // rows per split (48*64 = 3072)
#define BK     96      // GEMM k-tile per CTA
#define KC     32      // k-chunk staged in smem
#define NSPLIT 32      // D / BK
#define BM     128     // GEMM m-tile
#define MT     4       // BATCH / BM
#define ZSTR   33      // Zs row stride (33 mod 32 = 1 -> conflict-free)
#define WSTR   102     // Wt row stride (even -> aligned float2 reads)
#define OSTR   101     // output staging stride (odd -> conflict-free)

// ---- device scratch (static, no allocation) ----
__device__ float g_pA[RS * D];
__device__ float g_pB[RS * D];
__device__ float g_colA[D];
__device__ float g_colB[D];
__device__ float g_fcrow[NC];
__device__ float g_part1;
__device__ float g_scratch[NSPLIT * BATCH * NC];   // 6.55 MB (L2-resident)

// ---- f32x2 packed-FMA helpers (sm_103a FFMA2) ----
__device__ __forceinline__ unsigned long long pk2(float lo, float hi) {
    unsigned long long r;
    asm("mov.b64 %0, {%1, %2};" : "=l"(r) : "f"(lo), "f"(hi));
    return r;
}
__device__ __forceinline__ void fma2(unsigned long long& d,
                                     unsigned long long a,
                                     unsigned long long b) {
    asm("fma.rn.f32x2 %0, %1, %2, %0;" : "+l"(d) : "l"(a), "l"(b));
}
__device__ __forceinline__ float2 up2(unsigned long long v) {
    float2 f;
    asm("mov.b64 {%0, %1}, %2;" : "=f"(f.x), "=f"(f.y) : "l"(v));
    return f;
}

// ---- FMA-pipe sincos (no MUFU). Valid for |x| < ~1e5; here |x|<6. ----
// Quadrant via magic-number round, 2-term Cody-Waite, deg-7 sin / deg-8 cos
// minimax on [-pi/4, pi/4]. Abs err ~1e-7.
__device__ __forceinline__ void fast_sincos(float x, float& sn, float& cs) {
    const float BIGMAGIC = 12582912.0f;               // 1.5 * 2^23
    float y = fmaf(x, 0.63661977236758134f, BIGMAGIC);
    unsigned q = __float_as_uint(y);                  // low 2 bits = quadrant
    float n = y - BIGMAGIC;
    float r = fmaf(n, -1.57079637050628662109375f, x);    // pi/2 hi
    r = fmaf(n, 4.37113900018624283e-8f, r);              // -(pi/2 - hi)
    float r2 = r * r;
    // sin poly: r + r*r2*(s1 + r2*(s2 + r2*s3))
    float ps = fmaf(r2, -1.9515295891e-4f, 8.3321608736e-3f);
    ps = fmaf(r2, ps, -1.6666654611e-1f);
    float sinp = fmaf(r * r2, ps, r);
    // cos poly: 1 + r2*(-0.5 + r2*(c2 + r2*(c3 + r2*c4)))
    float pc = fmaf(r2, 2.443315711809948e-5f, -1.388731625493765e-3f);
    pc = fmaf(r2, pc, 4.166664568298827e-2f);
    pc = fmaf(r2, pc, -0.5f);
    float cosp = fmaf(r2, pc, 1.0f);
    // quadrant swap + sign
    bool swap = (q & 1u);
    float us = swap ? cosp : sinp;
    float uc = swap ? sinp : cosp;
    sn = __uint_as_float(__float_as_uint(us) ^ ((q & 2u) << 30));
    cs = __uint_as_float(__float_as_uint(uc) ^ (((q + 1u) & 2u) << 30));
}

// ============================================================
// K1: partial column sums of a and b (vectorized float4). HBM-bound.
// ============================================================
__global__ void k1_colsum_partial(const float4* __restrict__ a,
                                  const float4* __restrict__ b) {
    int d4 = blockIdx.x * 256 + threadIdx.x;       // 0..767
    int rs = blockIdx.y;
    const float4* src = (blockIdx.z == 0) ? a : b;
    float*        dst = (blockIdx.z == 0) ? g_pA : g_pB;
    const float4* p = src + rs * RROWS * (D / 4) + d4;
    float4 acc = make_float4(0.f, 0.f, 0.f, 0.f);
#pragma unroll 8
    for (int r = 0; r < RROWS; r++) {
        float4 v = p[r * (D / 4)];
        acc.x += v.x; acc.y += v.y; acc.z += v.z; acc.w += v.w;
    }
    *reinterpret_cast<float4*>(dst + rs * D + d4 * 4) = acc;
}

// ============================================================
// K2: finalize column sums; fc_w row sums; scalar part1.
// ============================================================
__global__ void k2_finalize(const float* __restrict__ fc_w,
                            const float* __restrict__ w,
                            const float* __restrict__ n_param) {
    int bx = blockIdx.x, t = threadIdx.x;
    if (bx < 12) {
        int d = bx * 256 + t;
        float sa = 0.f, sb = 0.f;
#pragma unroll 8
        for (int s = 0; s < RS; s++) {
            sa += g_pA[s * D + d];
            sb += g_pB[s * D + d];
        }
        g_colA[d] = sa;
        g_colB[d] = sb;
    } else {
        int c    = (bx - 12) * 8 + (t >> 5);
        int lane = t & 31;
        if (c < NC) {
            float s = 0.f;
            for (int j = lane; j < D; j += 32) s += fc_w[c * D + j];
#pragma unroll
            for (int o = 16; o; o >>= 1) s += __shfl_xor_sync(0xffffffffu, s, o);
            if (lane == 0) g_fcrow[c] = s;
        }
        if (bx == 24 && t == 0) {
            float p1 = 0.f;
#pragma unroll
            for (int i = 0; i < 4; i++)
                p1 += w[i + 1] * n_param[i + 1] + w[i] * n_param[i];
            g_part1 = p1;
        }
    }
}

// ============================================================
// K3: fused split-K GEMM, packed f32x2 FMA, polynomial sincos.
// grid (4, 32) = 128 CTAs, block 320 (10 warps).
// ============================================================
__global__ __launch_bounds__(320, 2)
void k3_gemm(const float* __restrict__ xf, const float* __restrict__ fc_w) {
    __shared__ float sm[BM * ZSTR + KC * WSTR];   // 4224 + 3264 floats = 29.9KB
    float* Zs = sm;                                // [128][33]
    float* Wt = sm + BM * ZSTR;                    // [32][102]

    const int t     = threadIdx.x;
    const int lane  = t & 31;
    const int wrp   = t >> 5;                      // 0..9 -> column group
    const int mtile = blockIdx.x;
    const int split = blockIdx.y;
    const int k0    = split * BK;

    unsigned long long acc[4][5];
#pragma unroll
    for (int m = 0; m < 4; m++)
#pragma unroll
        for (int n = 0; n < 5; n++) acc[m][n] = 0ull;

    for (int chunk = 0; chunk < BK / KC; chunk++) {
        const int kc = k0 + chunk * KC;

        // ---- Z chunk: 128 rows x 8 quads, poly sincos on FMA pipe ----
        for (int i = t; i < BM * (KC / 4); i += 320) {
            int row = i >> 3;
            int kq  = i & 7;
            float4 v = *reinterpret_cast<const float4*>(
                xf + (mtile * BM + row) * D + kc + kq * 4);
            float vv[4] = {v.x, v.y, v.z, v.w};
#pragma unroll
            for (int j = 0; j < 4; j++) {
                int kk = kq * 4 + j;
                float sn, cs;
                fast_sincos(vv[j], sn, cs);
                Zs[row * ZSTR + kk] =
                    cs * g_colA[kc + kk] + sn * g_colB[kc + kk];
            }
        }
        // ---- W chunk: 100 rows x 8 quads, stored transposed ----
        for (int i = t; i < NC * (KC / 4); i += 320) {
            int c  = i >> 3;
            int kq = i & 7;
            float4 v = *reinterpret_cast<const float4*>(fc_w + c * D + kc + kq * 4);
            Wt[(kq * 4 + 0) * WSTR + c] = v.x;
            Wt[(kq * 4 + 1) * WSTR + c] = v.y;
            Wt[(kq * 4 + 2) * WSTR + c] = v.z;
            Wt[(kq * 4 + 3) * WSTR + c] = v.w;
        }
        __syncthreads();

#pragma unroll 4
        for (int k = 0; k < KC; k++) {
            unsigned long long wv[5];
            const float* wrow = &Wt[k * WSTR + wrp * 10];
#pragma unroll
            for (int n = 0; n < 5; n++) {
                float2 wp = *reinterpret_cast<const float2*>(wrow + 2 * n);
                wv[n] = pk2(wp.x, wp.y);
            }
#pragma unroll
            for (int m = 0; m < 4; m++) {
                float z = Zs[(lane + 32 * m) * ZSTR + k];
                unsigned long long zz = pk2(z, z);
#pragma unroll
                for (int n = 0; n < 5; n++) fma2(acc[m][n], zz, wv[n]);
            }
        }
        __syncthreads();
    }

    // ---- epilogue: stage in smem (2 halves), coalesced stores ----
    float* stage = sm;    // reuse: 64*101 = 6464 <= 7488 floats
#pragma unroll
    for (int half = 0; half < 2; half++) {
#pragma unroll
        for (int m2 = 0; m2 < 2; m2++) {
            int m = half * 2 + m2;
            int r = lane + 32 * m2;                // 0..63 local row
#pragma unroll
            for (int n = 0; n < 5; n++) {
                float2 v = up2(acc[m][n]);
                stage[r * OSTR + wrp * 10 + 2 * n]     = v.x;
                stage[r * OSTR + wrp * 10 + 2 * n + 1] = v.y;
            }
        }
        __syncthreads();
        float* dst = g_scratch + split * (BATCH * NC)
                   + (mtile * BM + half * 64) * NC;
        for (int i = t; i < 64 * NC; i += 320) {
            int row = i / NC;
            int c   = i - row * NC;
            dst[i] = stage[row * OSTR + c];
        }
        __syncthreads();
    }
}

// ============================================================
// K4: reduce 32 splits, 4-way parallel per output + smem combine.
// grid 800 x 256: 64 outputs/block, 4 slices of 8 splits each.
// ============================================================
__global__ void k4_final(const float* __restrict__ fc_b, float* __restrict__ out) {
    __shared__ float sm[3 * 64];
    int t  = threadIdx.x;
    int il = t & 63;           // local output index
    int sl = t >> 6;           // slice 0..3
    int idx = blockIdx.x * 64 + il;
    float v[8];
#pragma unroll
    for (int j = 0; j < 8; j++)
        v[j] = g_scratch[(sl * 8 + j) * (BATCH * NC) + idx];
    float s = ((v[0] + v[1]) + (v[2] + v[3])) + ((v[4] + v[5]) + (v[6] + v[7]));
    if (sl > 0) sm[(sl - 1) * 64 + il] = s;
    __syncthreads();
    if (sl == 0) {
        s += (sm[il] + sm[64 + il]) + sm[128 + il];
        int c = idx % NC;
        out[idx] = s + g_part1 * g_fcrow[c] + fc_b[c];
    }
}

// ============================================================
extern "C" void kernel_launch(void* const* d_in, const int* in_sizes, int n_in,
                              void* d_out, int out_size) {
    const float* x       = (const float*)d_in[0];   // [512,3072]
    const float* a       = (const float*)d_in[1];   // [3072,3072,1]
    const float* b       = (const float*)d_in[2];   // [3072,3072,1]
    const float* w       = (const float*)d_in[3];   // [5]
    const float* n_param = (const float*)d_in[4];   // [5]
    const float* fc_w    = (const float*)d_in[5];   // [100,3072]
    const float* fc_b    = (const float*)d_in[6];   // [100]
    float* out = (float*)d_out;                     // [512,100]

    k1_colsum_partial<<<dim3(3, RS, 2), 256>>>((const float4*)a, (const float4*)b);
    k2_finalize<<<25, 256>>>(fc_w, w, n_param);
    k3_gemm<<<dim3(MT, NSPLIT), 320>>>(x, fc_w);
    k4_final<<<800, 256>>>(fc_b, out);
}